// round 13
// baseline (speedup 1.0000x reference)
#include <cuda_runtime.h>
#include <cuda_fp16.h>
#include <math.h>
#include <stdint.h>

// Problem constants
#define BB 2
#define TT 1024
#define DMODEL 3072
#define NHEADS 32
#define NKV 8
#define HD 96
#define NTOK 2048
#define QDIM 3072
#define KVDIM 768
#define QKVN 4608            // fused projection width (q|k|v)
#define VOFF (QDIM + KVDIM)  // 3840: start of v columns

// Scratch (static device globals; no allocation allowed)
__device__ __half g_xh[(size_t)NTOK*DMODEL];
__device__ __half g_wh[(size_t)QKVN*DMODEL];     // [wq;wk;wv] fp16
__device__ __half g_woh[(size_t)DMODEL*QDIM];
__device__ __half g_qkvh[(size_t)NTOK*QKVN];     // q|k (v-tiles bypassed to g_vT)
__device__ __half g_vT[(size_t)BB*NKV*HD*TT];    // V transposed: [b*kvh][dim][tok]
__device__ __half g_attnh[(size_t)NTOK*QDIM];    // attention output fp16

// ---------------------------------------------------------------------------
// Helpers
// ---------------------------------------------------------------------------
__device__ __forceinline__ uint32_t smem_u32(const void* p) {
    uint32_t a;
    asm("{ .reg .u64 t; cvta.to.shared.u64 t, %1; cvt.u32.u64 %0, t; }"
        : "=r"(a) : "l"(p));
    return a;
}

#define MMA_F16(acc, a, b)                                                    \
    asm volatile(                                                             \
        "mma.sync.aligned.m16n8k16.row.col.f32.f16.f16.f32 "                  \
        "{%0,%1,%2,%3}, {%4,%5,%6,%7}, {%8,%9}, {%0,%1,%2,%3};"               \
        : "+f"((acc)[0]), "+f"((acc)[1]), "+f"((acc)[2]), "+f"((acc)[3])      \
        : "r"((a)[0]), "r"((a)[1]), "r"((a)[2]), "r"((a)[3]),                 \
          "r"((b)[0]), "r"((b)[1]))

#define LDSM_X4(r, addr)                                                      \
    asm volatile("ldmatrix.sync.aligned.m8n8.x4.shared.b16 {%0,%1,%2,%3}, [%4];" \
        : "=r"((r)[0]), "=r"((r)[1]), "=r"((r)[2]), "=r"((r)[3]) : "r"(addr))

#define LDSM_X2(r, addr)                                                      \
    asm volatile("ldmatrix.sync.aligned.m8n8.x2.shared.b16 {%0,%1}, [%2];"    \
        : "=r"((r)[0]), "=r"((r)[1]) : "r"(addr))

#define CP_ASYNC16(dst, src)                                                  \
    asm volatile("cp.async.cg.shared.global [%0], [%1], 16;" :: "r"(dst), "l"(src))

// ---------------------------------------------------------------------------
// Fused fp32 -> fp16 conversion for all 5 tensors in one launch.
// ---------------------------------------------------------------------------
__device__ __forceinline__ uint4 pack8h(float4 a, float4 b) {
    __half2 h0 = __floats2half2_rn(a.x, a.y);
    __half2 h1 = __floats2half2_rn(a.z, a.w);
    __half2 h2 = __floats2half2_rn(b.x, b.y);
    __half2 h3 = __floats2half2_rn(b.z, b.w);
    uint4 r;
    r.x = *(uint32_t*)&h0; r.y = *(uint32_t*)&h1;
    r.z = *(uint32_t*)&h2; r.w = *(uint32_t*)&h3;
    return r;
}

__global__ void f2h_multi(const float* __restrict__ s0, __half* __restrict__ d0, int c0,
                          const float* __restrict__ s1, __half* __restrict__ d1, int c1,
                          const float* __restrict__ s2, __half* __restrict__ d2, int c2,
                          const float* __restrict__ s3, __half* __restrict__ d3, int c3,
                          const float* __restrict__ s4, __half* __restrict__ d4, int c4)
{
    int i = blockIdx.x * blockDim.x + threadIdx.x;
    const float* s; __half* d; int off;
    int e0 = c0, e1 = e0 + c1, e2 = e1 + c2, e3 = e2 + c3, e4 = e3 + c4;
    if      (i < e0) { s = s0; d = d0; off = i; }
    else if (i < e1) { s = s1; d = d1; off = i - e0; }
    else if (i < e2) { s = s2; d = d2; off = i - e1; }
    else if (i < e3) { s = s3; d = d3; off = i - e2; }
    else if (i < e4) { s = s4; d = d4; off = i - e3; }
    else return;

    const float4* sp = (const float4*)s + (size_t)off * 4;
    float4 a = sp[0], b = sp[1], c = sp[2], e = sp[3];
    uint4* dp = (uint4*)d + (size_t)off * 2;
    dp[0] = pack8h(a, b);
    dp[1] = pack8h(c, e);
}

// ---------------------------------------------------------------------------
// fp16 tensor-core GEMM: C[M,N] = A[M,K] * B[N,K]^T, fp32 accumulate.
// Block 256x128, K-tile 64, 16 warps (4x4), warp 64x32, mma m16n8k16,
// ldmatrix fragment loads, 2-stage cp.async double buffer (512 threads/CTA).
// VSPLIT: tiles with n0 >= VOFF write transposed fp16 to vT instead of C.
// Requires M%256==0, N%128==0, K%64==0.
// ---------------------------------------------------------------------------
#define HPITCH  72                    // halves per smem row
#define HPITCHB 144                   // bytes (16B-aligned: 16*9)
#define AB_OFF  (256 * HPITCHB)       // B offset within stage (36864)
#define STAGE2B ((256 + 128) * HPITCHB)  // 55296 per stage
#define HGEMM_SMEM (2 * STAGE2B)         // 110592

template <typename OutT, bool VSPLIT>
__global__ __launch_bounds__(512)
void gemm_h2(const __half* __restrict__ A, const __half* __restrict__ B,
             OutT* __restrict__ C, __half* __restrict__ vT, int M, int N, int K)
{
    extern __shared__ char smem[];
    const uint32_t sbase = smem_u32(smem);
    const int tid  = threadIdx.x;
    const int warp = tid >> 5;
    const int lane = tid & 31;
    const int g  = lane >> 2;
    const int tg = lane & 3;
    const int wm = warp & 3;          // 4 warps along M (64 each = 256)
    const int wn = warp >> 2;         // 4 warps along N (32 each = 128)
    const int m0 = blockIdx.y * 256;
    const int n0 = blockIdx.x * 128;

    float acc[4][4][4];
#pragma unroll
    for (int i = 0; i < 4; i++)
#pragma unroll
        for (int j = 0; j < 4; j++)
#pragma unroll
            for (int r = 0; r < 4; r++) acc[i][j][r] = 0.f;

    const uint32_t aoff = ((lane & 15) * HPITCH + (lane >> 4) * 8) * 2;
    const uint32_t boff = ((lane & 7) * HPITCH + ((lane >> 3) & 1) * 8) * 2;

    auto load_stage = [&](int s, int k0) {
        const uint32_t stg = sbase + s * STAGE2B;
#pragma unroll
        for (int i = 0; i < 6; i++) {
            int c = tid + i * 512;
            if (c < 2048) {
                int r = c >> 3, cc = c & 7;
                CP_ASYNC16(stg + r * HPITCHB + cc * 16,
                           A + (size_t)(m0 + r) * K + k0 + cc * 8);
            } else {
                int cb = c - 2048;
                int r = cb >> 3, cc = cb & 7;
                CP_ASYNC16(stg + AB_OFF + r * HPITCHB + cc * 16,
                           B + (size_t)(n0 + r) * K + k0 + cc * 8);
            }
        }
    };

    const int nkt = K / 64;

    load_stage(0, 0);
    asm volatile("cp.async.commit_group;");

    for (int kt = 0; kt < nkt; kt++) {
        const int cur = kt & 1;
        if (kt + 1 < nkt) {
            load_stage(cur ^ 1, (kt + 1) * 64);
            asm volatile("cp.async.commit_group;");
            asm volatile("cp.async.wait_group 1;");
        } else {
            asm volatile("cp.async.wait_group 0;");
        }
        __syncthreads();

        const uint32_t stgA = sbase + cur * STAGE2B + wm * 64 * HPITCHB + aoff;
        const uint32_t stgB = sbase + cur * STAGE2B + AB_OFF + wn * 32 * HPITCHB + boff;

#pragma unroll
        for (int ks = 0; ks < 4; ks++) {
            uint32_t af[4][4], bf[4][2];
#pragma unroll
            for (int mi = 0; mi < 4; mi++)
                LDSM_X4(af[mi], stgA + mi * 16 * HPITCHB + ks * 32);
#pragma unroll
            for (int ni = 0; ni < 4; ni++)
                LDSM_X2(bf[ni], stgB + ni * 8 * HPITCHB + ks * 32);
#pragma unroll
            for (int mi = 0; mi < 4; mi++)
#pragma unroll
                for (int ni = 0; ni < 4; ni++)
                    MMA_F16(acc[mi][ni], af[mi], bf[ni]);
        }
        __syncthreads();
    }

    if (VSPLIT && n0 >= VOFF) {
        // V tile: write transposed fp16 directly to vT[b*kvh][dim][tok]
#pragma unroll
        for (int mi = 0; mi < 4; mi++) {
            int row = m0 + wm * 64 + mi * 16 + g;
            int bb  = row >> 10;            // /TT
            int tok = row & (TT - 1);
#pragma unroll
            for (int ni = 0; ni < 4; ni++) {
                int col = n0 + wn * 32 + ni * 8 + 2 * tg;
                int cc  = col - VOFF;
                int kvh = cc / HD;
                int d   = cc % HD;
                __half* dst = vT + ((size_t)(bb * NKV + kvh) * HD + d) * TT + tok;
                dst[0]      = __float2half_rn(acc[mi][ni][0]);
                dst[TT]     = __float2half_rn(acc[mi][ni][1]);
                dst[8]      = __float2half_rn(acc[mi][ni][2]);
                dst[TT + 8] = __float2half_rn(acc[mi][ni][3]);
            }
        }
    } else {
#pragma unroll
        for (int mi = 0; mi < 4; mi++) {
            int row = m0 + wm * 64 + mi * 16 + g;
#pragma unroll
            for (int ni = 0; ni < 4; ni++) {
                int col = n0 + wn * 32 + ni * 8 + 2 * tg;
                if (sizeof(OutT) == 2) {
                    __half* cp = (__half*)C;
                    *(__half2*)&cp[(size_t)row * N + col] =
                        __floats2half2_rn(acc[mi][ni][0], acc[mi][ni][1]);
                    *(__half2*)&cp[(size_t)(row + 8) * N + col] =
                        __floats2half2_rn(acc[mi][ni][2], acc[mi][ni][3]);
                } else {
                    float* cp = (float*)C;
                    *(float2*)&cp[(size_t)row * N + col] =
                        make_float2(acc[mi][ni][0], acc[mi][ni][1]);
                    *(float2*)&cp[(size_t)(row + 8) * N + col] =
                        make_float2(acc[mi][ni][2], acc[mi][ni][3]);
                }
            }
        }
    }
}

// ---------------------------------------------------------------------------
// Fused RMSNorm + RoPE for BOTH q and k in one launch, fp16 in-place.
// ---------------------------------------------------------------------------
__global__ void norm_rope_qk_kernel(__half* __restrict__ qkv,
                                    const float* __restrict__ wq,
                                    const float* __restrict__ wk,
                                    const float* __restrict__ cosb,
                                    const float* __restrict__ sinb,
                                    int rows_q, int rows_total, float qscale)
{
    int gw = (blockIdx.x * blockDim.x + threadIdx.x) >> 5;
    if (gw >= rows_total) return;
    int lane = threadIdx.x & 31;

    const float* w;
    __half* row;
    float outscale;
    int tok;
    if (gw < rows_q) {
        int h = gw & (NHEADS - 1);
        tok = gw >> 5;
        row = qkv + (size_t)tok * QKVN + (size_t)h * HD;
        w = wq; outscale = qscale;
    } else {
        int gk = gw - rows_q;
        int h = gk & (NKV - 1);
        tok = gk >> 3;
        row = qkv + (size_t)tok * QKVN + QDIM + (size_t)h * HD;
        w = wk; outscale = 1.0f;
    }
    int tpos = tok & (TT - 1);

    float2 v0 = __half22float2(*(const __half2*)&row[2 * lane]);
    float2 v1 = make_float2(0.f, 0.f);
    if (lane < 16) v1 = __half22float2(*(const __half2*)&row[2 * (lane + 32)]);

    float ss = v0.x*v0.x + v0.y*v0.y + v1.x*v1.x + v1.y*v1.y;
#pragma unroll
    for (int off = 16; off; off >>= 1)
        ss += __shfl_xor_sync(0xffffffffu, ss, off);
    float inv = outscale / sqrtf(ss * (1.0f / HD) + 1e-6f);

    const float* cr = cosb + (size_t)tpos * HD;
    const float* sr = sinb + (size_t)tpos * HD;
    {
        int i2 = 2 * lane;
        float xr = w[i2] * v0.x * inv;
        float xi = w[i2 + 1] * v0.y * inv;
        float o0 = xr * cr[i2]     - xi * sr[i2];
        float o1 = xr * sr[i2 + 1] + xi * cr[i2 + 1];
        *(__half2*)&row[i2] = __floats2half2_rn(o0, o1);
    }
    if (lane < 16) {
        int i2 = 2 * (lane + 32);
        float xr = w[i2] * v1.x * inv;
        float xi = w[i2 + 1] * v1.y * inv;
        float o0 = xr * cr[i2]     - xi * sr[i2];
        float o1 = xr * sr[i2 + 1] + xi * cr[i2 + 1];
        *(__half2*)&row[i2] = __floats2half2_rn(o0, o1);
    }
}

// ---------------------------------------------------------------------------
// fp16 tensor-core flash attention (FlashAttention-2 style).
// Block = (128 q-rows, head, batch), 8 warps x 16 rows. 1 CTA/SM (reg-heavy).
// ---------------------------------------------------------------------------
#define KP   52
#define VP   36
#define K_STG_B   (64 * 104 * 2)
#define VT_STG_B  (96 * 72 * 2)
#define AKV_STG_B (K_STG_B + VT_STG_B)
#define PP   36
#define ATTN_SMEM_B (2 * AKV_STG_B + 8 * 16 * PP * 4)   // 72704

__global__ __launch_bounds__(256, 1)
void attn_h_kernel(const __half* __restrict__ qk, const __half* __restrict__ vT,
                   __half* __restrict__ o)
{
    extern __shared__ char smem[];
    const int tid  = threadIdx.x;
    const int warp = tid >> 5;
    const int lane = tid & 31;
    const int g    = lane >> 2;
    const int tg   = lane & 3;

    const int qt = blockIdx.x;
    const int h  = blockIdx.y;
    const int b  = blockIdx.z;
    const int kvh = h >> 2;
    const int q0 = qt * 128;
    const int row0 = warp * 16;

    const __half* qb  = qk + (size_t)b * TT * QKVN + (size_t)h * HD;
    const __half* kb  = qk + (size_t)b * TT * QKVN + QDIM + (size_t)kvh * HD;
    const __half* vTb = vT + (size_t)(b * NKV + kvh) * HD * TT;
    __half*       ob  = o  + (size_t)b * TT * QDIM + (size_t)h * HD;

    uint32_t* Psu = (uint32_t*)(smem + 2 * AKV_STG_B) + warp * 16 * PP;

    // --- Q fragments (pre-scaled fp16 in global) ---
    uint32_t qf[6][4];
    {
        const __half* r0p = qb + (size_t)(q0 + row0 + g)     * QKVN;
        const __half* r8p = qb + (size_t)(q0 + row0 + g + 8) * QKVN;
#pragma unroll
        for (int ks = 0; ks < 6; ks++) {
            qf[ks][0] = *(const uint32_t*)&r0p[ks * 16 + 2 * tg];
            qf[ks][1] = *(const uint32_t*)&r8p[ks * 16 + 2 * tg];
            qf[ks][2] = *(const uint32_t*)&r0p[ks * 16 + 2 * tg + 8];
            qf[ks][3] = *(const uint32_t*)&r8p[ks * 16 + 2 * tg + 8];
        }
    }

    float oacc[12][4];
#pragma unroll
    for (int i = 0; i < 12; i++)
#pragma unroll
        for (int j = 0; j < 4; j++) oacc[i][j] = 0.f;

    float m0 = -1e30f, m1 = -1e30f, l0 = 0.f, l1 = 0.f;
    const int nt = 2 * qt + 2;

    auto load_kv = [&](int stage, int kt) {
        const uint32_t stg = smem_u32(smem) + stage * AKV_STG_B;
#pragma unroll
        for (int j = 0; j < 6; j++) {
            int c = tid + j * 256;
            if (c < 768) {
                int r = c / 12, cc = c % 12;
                CP_ASYNC16(stg + r * 208 + cc * 16,
                           kb + (size_t)(kt * 64 + r) * QKVN + cc * 8);
            } else {
                int c2 = c - 768;
                int r = c2 >> 3, cc = c2 & 7;
                CP_ASYNC16(stg + K_STG_B + r * 144 + cc * 16,
                           vTb + (size_t)r * TT + kt * 64 + cc * 8);
            }
        }
    };

    load_kv(0, 0);
    asm volatile("cp.async.commit_group;");

    for (int kt = 0; kt < nt; kt++) {
        int cur = kt & 1;
        if (kt + 1 < nt) {
            load_kv(cur ^ 1, kt + 1);
            asm volatile("cp.async.commit_group;");
            asm volatile("cp.async.wait_group 1;");
        } else {
            asm volatile("cp.async.wait_group 0;");
        }
        __syncthreads();

        const uint32_t* Ksu = (const uint32_t*)(smem + cur * AKV_STG_B);
        const uint32_t* VTu = (const uint32_t*)(smem + cur * AKV_STG_B + K_STG_B);

        // --- S = Q K^T (16x64 per warp) ---
        float sacc[8][4];
#pragma unroll
        for (int i = 0; i < 8; i++)
#pragma unroll
            for (int j = 0; j < 4; j++) sacc[i][j] = 0.f;

#pragma unroll
        for (int ks = 0; ks < 6; ks++) {
#pragma unroll
            for (int ni = 0; ni < 8; ni++) {
                uint32_t bf[2];
                bf[0] = Ksu[(ni * 8 + g) * KP + ks * 8 + tg];
                bf[1] = Ksu[(ni * 8 + g) * KP + ks * 8 + tg + 4];
                MMA_F16(sacc[ni], qf[ks], bf);
            }
        }

        // --- Causal mask ---
        const int rg = q0 + row0 + g;
        const int r8 = rg + 8;
        if (kt >= 2 * qt) {
#pragma unroll
            for (int ni = 0; ni < 8; ni++) {
                int kbase = kt * 64 + ni * 8 + 2 * tg;
                if (kbase     > rg) sacc[ni][0] = -1e30f;
                if (kbase + 1 > rg) sacc[ni][1] = -1e30f;
                if (kbase     > r8) sacc[ni][2] = -1e30f;
                if (kbase + 1 > r8) sacc[ni][3] = -1e30f;
            }
        }

        // --- Online softmax (rows g, g+8) ---
        float mx0 = -1e30f, mx1 = -1e30f;
#pragma unroll
        for (int ni = 0; ni < 8; ni++) {
            mx0 = fmaxf(mx0, fmaxf(sacc[ni][0], sacc[ni][1]));
            mx1 = fmaxf(mx1, fmaxf(sacc[ni][2], sacc[ni][3]));
        }
        mx0 = fmaxf(mx0, __shfl_xor_sync(0xffffffffu, mx0, 1));
        mx0 = fmaxf(mx0, __shfl_xor_sync(0xffffffffu, mx0, 2));
        mx1 = fmaxf(mx1, __shfl_xor_sync(0xffffffffu, mx1, 1));
        mx1 = fmaxf(mx1, __shfl_xor_sync(0xffffffffu, mx1, 2));

        float mn0 = fmaxf(m0, mx0), mn1 = fmaxf(m1, mx1);
        float a0 = __expf(m0 - mn0), a1 = __expf(m1 - mn1);
        float s0 = 0.f, s1 = 0.f;
#pragma unroll
        for (int ni = 0; ni < 8; ni++) {
            float p0 = __expf(sacc[ni][0] - mn0);
            float p1 = __expf(sacc[ni][1] - mn0);
            float p2 = __expf(sacc[ni][2] - mn1);
            float p3 = __expf(sacc[ni][3] - mn1);
            sacc[ni][0] = p0; sacc[ni][1] = p1;
            sacc[ni][2] = p2; sacc[ni][3] = p3;
            s0 += p0 + p1; s1 += p2 + p3;
        }
        s0 += __shfl_xor_sync(0xffffffffu, s0, 1);
        s0 += __shfl_xor_sync(0xffffffffu, s0, 2);
        s1 += __shfl_xor_sync(0xffffffffu, s1, 1);
        s1 += __shfl_xor_sync(0xffffffffu, s1, 2);
        l0 = l0 * a0 + s0; l1 = l1 * a1 + s1;
        m0 = mn0; m1 = mn1;

#pragma unroll
        for (int nn = 0; nn < 12; nn++) {
            oacc[nn][0] *= a0; oacc[nn][1] *= a0;
            oacc[nn][2] *= a1; oacc[nn][3] *= a1;
        }

        // --- P -> per-warp smem (fp16) ---
        __syncwarp();
#pragma unroll
        for (int ni = 0; ni < 8; ni++) {
            __half2 h0 = __floats2half2_rn(sacc[ni][0], sacc[ni][1]);
            __half2 h1 = __floats2half2_rn(sacc[ni][2], sacc[ni][3]);
            Psu[g * PP + ni * 4 + tg]       = *(uint32_t*)&h0;
            Psu[(g + 8) * PP + ni * 4 + tg] = *(uint32_t*)&h1;
        }
        __syncwarp();

        // --- O += P V (V^T layout) ---
#pragma unroll
        for (int kk = 0; kk < 4; kk++) {
            uint32_t af[4];
            af[0] = Psu[g * PP + kk * 8 + tg];
            af[1] = Psu[(g + 8) * PP + kk * 8 + tg];
            af[2] = Psu[g * PP + kk * 8 + tg + 4];
            af[3] = Psu[(g + 8) * PP + kk * 8 + tg + 4];
#pragma unroll
            for (int nn = 0; nn < 12; nn++) {
                uint32_t bf[2];
                bf[0] = VTu[(nn * 8 + g) * VP + kk * 8 + tg];
                bf[1] = VTu[(nn * 8 + g) * VP + kk * 8 + tg + 4];
                MMA_F16(oacc[nn], af, bf);
            }
        }
        __syncthreads();   // protect KV stage reuse
    }

    // --- Epilogue: normalize, convert fp16, store ---
    float i0 = 1.f / l0, i1 = 1.f / l1;
    __half2* o0 = (__half2*)(ob + (size_t)(q0 + row0 + g)     * QDIM);
    __half2* o8 = (__half2*)(ob + (size_t)(q0 + row0 + g + 8) * QDIM);
#pragma unroll
    for (int nn = 0; nn < 12; nn++) {
        o0[nn * 4 + tg] = __floats2half2_rn(oacc[nn][0] * i0, oacc[nn][1] * i0);
        o8[nn * 4 + tg] = __floats2half2_rn(oacc[nn][2] * i1, oacc[nn][3] * i1);
    }
}

// ---------------------------------------------------------------------------
// Launch
// ---------------------------------------------------------------------------
extern "C" void kernel_launch(void* const* d_in, const int* in_sizes, int n_in,
                              void* d_out, int out_size)
{
    const float* x    = (const float*)d_in[0];
    const float* wq   = (const float*)d_in[2];
    const float* wk   = (const float*)d_in[3];
    const float* wv   = (const float*)d_in[4];
    const float* wo   = (const float*)d_in[5];
    const float* qnw  = (const float*)d_in[6];
    const float* knw  = (const float*)d_in[7];
    const float* cosb = (const float*)d_in[8];
    const float* sinb = (const float*)d_in[9];
    float* out = (float*)d_out;

    void *pxh, *pwh, *pwoh, *pqkvh, *pvT, *pah;
    cudaGetSymbolAddress(&pxh,   g_xh);
    cudaGetSymbolAddress(&pwh,   g_wh);
    cudaGetSymbolAddress(&pwoh,  g_woh);
    cudaGetSymbolAddress(&pqkvh, g_qkvh);
    cudaGetSymbolAddress(&pvT,   g_vT);
    cudaGetSymbolAddress(&pah,   g_attnh);
    __half* hx   = (__half*)pxh;
    __half* hw   = (__half*)pwh;
    __half* hwo  = (__half*)pwoh;
    __half* hqkv = (__half*)pqkvh;
    __half* hvT  = (__half*)pvT;
    __half* ha   = (__half*)pah;

    cudaFuncSetAttribute((void*)gemm_h2<__half, true>,
                         cudaFuncAttributeMaxDynamicSharedMemorySize, HGEMM_SMEM);
    cudaFuncSetAttribute((void*)gemm_h2<float, false>,
                         cudaFuncAttributeMaxDynamicSharedMemorySize, HGEMM_SMEM);
    cudaFuncSetAttribute(attn_h_kernel, cudaFuncAttributeMaxDynamicSharedMemorySize,
                         ATTN_SMEM_B);

    dim3 blk(256);
    dim3 blk512(512);

    // Fused fp16 conversion pre-pass (x, wq, wk, wv, wo) — one launch.
    {
        const int cx  = NTOK * DMODEL / 16;
        const int cwq = QDIM * DMODEL / 16;
        const int cwk = KVDIM * DMODEL / 16;
        const int cwv = KVDIM * DMODEL / 16;
        const int cwo = DMODEL * QDIM / 16;
        const int total = cx + cwq + cwk + cwv + cwo;
        f2h_multi<<<(total + 255) / 256, blk>>>(
            x,  hx,  cx,
            wq, hw,  cwq,
            wk, hw + (size_t)QDIM * DMODEL, cwk,
            wv, hw + (size_t)(QDIM + KVDIM) * DMODEL, cwv,
            wo, hwo, cwo);
    }

    // Fused QKV projection: q|k -> g_qkvh, v-tiles transposed -> g_vT
    gemm_h2<__half, true><<<dim3(QKVN / 128, NTOK / 256), blk512, HGEMM_SMEM>>>(
        hx, hw, hqkv, hvT, NTOK, QKVN, DMODEL);

    // RMSNorm + RoPE in place, q and k in one launch (q scaled by 1/sqrt(96))
    {
        const float scale = 0.1020620726159658f;
        int rows_q = NTOK * NHEADS;
        int rows_total = rows_q + NTOK * NKV;
        norm_rope_qk_kernel<<<(rows_total * 32 + 255) / 256, blk>>>(
            hqkv, qnw, knw, cosb, sinb, rows_q, rows_total, scale);
    }

    // Attention (fp16 HMMA, 1 CTA/SM — reg-heavy, do NOT cap regs)
    attn_h_kernel<<<dim3(TT / 128, NHEADS, BB), blk, ATTN_SMEM_B>>>(hqkv, hvT, ha);

    // Output projection (fp32 out)
    gemm_h2<float, false><<<dim3(QDIM / 128, NTOK / 256), blk512, HGEMM_SMEM>>>(
        ha, hwo, out, nullptr, NTOK, QDIM, DMODEL);
}

// round 14
// speedup vs baseline: 1.1177x; 1.1177x over previous
#include <cuda_runtime.h>
#include <cuda_fp16.h>
#include <math.h>
#include <stdint.h>

// Problem constants
#define BB 2
#define TT 1024
#define DMODEL 3072
#define NHEADS 32
#define NKV 8
#define HD 96
#define NTOK 2048
#define QDIM 3072
#define KVDIM 768
#define QKVN 4608            // fused projection width (q|k|v)
#define VOFF (QDIM + KVDIM)  // 3840: start of v columns

// Scratch (static device globals; no allocation allowed)
__device__ __half g_xh[(size_t)NTOK*DMODEL];
__device__ __half g_wh[(size_t)QKVN*DMODEL];     // [wq;wk;wv] fp16
__device__ __half g_woh[(size_t)DMODEL*QDIM];
__device__ __half g_qkvh[(size_t)NTOK*QKVN];     // q|k (v-tiles bypassed to g_vT)
__device__ __half g_vT[(size_t)BB*NKV*HD*TT];    // V transposed: [b*kvh][dim][tok]
__device__ __half g_attnh[(size_t)NTOK*QDIM];    // attention output fp16

// ---------------------------------------------------------------------------
// Helpers
// ---------------------------------------------------------------------------
__device__ __forceinline__ uint32_t smem_u32(const void* p) {
    uint32_t a;
    asm("{ .reg .u64 t; cvta.to.shared.u64 t, %1; cvt.u32.u64 %0, t; }"
        : "=r"(a) : "l"(p));
    return a;
}

#define MMA_F16(acc, a, b)                                                    \
    asm volatile(                                                             \
        "mma.sync.aligned.m16n8k16.row.col.f32.f16.f16.f32 "                  \
        "{%0,%1,%2,%3}, {%4,%5,%6,%7}, {%8,%9}, {%0,%1,%2,%3};"               \
        : "+f"((acc)[0]), "+f"((acc)[1]), "+f"((acc)[2]), "+f"((acc)[3])      \
        : "r"((a)[0]), "r"((a)[1]), "r"((a)[2]), "r"((a)[3]),                 \
          "r"((b)[0]), "r"((b)[1]))

#define LDSM_X4(r, addr)                                                      \
    asm volatile("ldmatrix.sync.aligned.m8n8.x4.shared.b16 {%0,%1,%2,%3}, [%4];" \
        : "=r"((r)[0]), "=r"((r)[1]), "=r"((r)[2]), "=r"((r)[3]) : "r"(addr))

#define LDSM_X2(r, addr)                                                      \
    asm volatile("ldmatrix.sync.aligned.m8n8.x2.shared.b16 {%0,%1}, [%2];"    \
        : "=r"((r)[0]), "=r"((r)[1]) : "r"(addr))

#define CP_ASYNC16(dst, src)                                                  \
    asm volatile("cp.async.cg.shared.global [%0], [%1], 16;" :: "r"(dst), "l"(src))

// ---------------------------------------------------------------------------
// Fused fp32 -> fp16 conversion for all 5 tensors in one launch.
// ---------------------------------------------------------------------------
__device__ __forceinline__ uint4 pack8h(float4 a, float4 b) {
    __half2 h0 = __floats2half2_rn(a.x, a.y);
    __half2 h1 = __floats2half2_rn(a.z, a.w);
    __half2 h2 = __floats2half2_rn(b.x, b.y);
    __half2 h3 = __floats2half2_rn(b.z, b.w);
    uint4 r;
    r.x = *(uint32_t*)&h0; r.y = *(uint32_t*)&h1;
    r.z = *(uint32_t*)&h2; r.w = *(uint32_t*)&h3;
    return r;
}

__global__ void f2h_multi(const float* __restrict__ s0, __half* __restrict__ d0, int c0,
                          const float* __restrict__ s1, __half* __restrict__ d1, int c1,
                          const float* __restrict__ s2, __half* __restrict__ d2, int c2,
                          const float* __restrict__ s3, __half* __restrict__ d3, int c3,
                          const float* __restrict__ s4, __half* __restrict__ d4, int c4)
{
    int i = blockIdx.x * blockDim.x + threadIdx.x;
    const float* s; __half* d; int off;
    int e0 = c0, e1 = e0 + c1, e2 = e1 + c2, e3 = e2 + c3, e4 = e3 + c4;
    if      (i < e0) { s = s0; d = d0; off = i; }
    else if (i < e1) { s = s1; d = d1; off = i - e0; }
    else if (i < e2) { s = s2; d = d2; off = i - e1; }
    else if (i < e3) { s = s3; d = d3; off = i - e2; }
    else if (i < e4) { s = s4; d = d4; off = i - e3; }
    else return;

    const float4* sp = (const float4*)s + (size_t)off * 4;
    float4 a = sp[0], b = sp[1], c = sp[2], e = sp[3];
    uint4* dp = (uint4*)d + (size_t)off * 2;
    dp[0] = pack8h(a, b);
    dp[1] = pack8h(c, e);
}

// ---------------------------------------------------------------------------
// fp16 tensor-core GEMM: C[M,N] = A[M,K] * B[N,K]^T, fp32 accumulate.
// Block 128x128, K-tile 64, 8 warps (2x4), warp 64x32, mma m16n8k16,
// ldmatrix fragment loads, 2-stage cp.async double buffer (2 CTAs/SM).
// VSPLIT: tiles with n0 >= VOFF write transposed fp16 to vT instead of C.
// ---------------------------------------------------------------------------
#define HPITCH  72                    // halves per smem row
#define HPITCHB 144                   // bytes (16B-aligned: 16*9)
#define HSTG    (128 * HPITCHB)       // 18432 per matrix
#define HSTAGE  (2 * HSTG)            // 36864 per stage (A+B)
#define HGEMM_SMEM (2 * HSTAGE)       // 73728

template <typename OutT, bool VSPLIT>
__global__ __launch_bounds__(256)
void gemm_h(const __half* __restrict__ A, const __half* __restrict__ B,
            OutT* __restrict__ C, __half* __restrict__ vT, int M, int N, int K)
{
    extern __shared__ char smem[];
    const uint32_t sbase = smem_u32(smem);
    const int tid  = threadIdx.x;
    const int warp = tid >> 5;
    const int lane = tid & 31;
    const int g  = lane >> 2;
    const int tg = lane & 3;
    const int wm = warp & 1;
    const int wn = warp >> 1;
    const int m0 = blockIdx.y * 128;
    const int n0 = blockIdx.x * 128;

    float acc[4][4][4];
#pragma unroll
    for (int i = 0; i < 4; i++)
#pragma unroll
        for (int j = 0; j < 4; j++)
#pragma unroll
            for (int r = 0; r < 4; r++) acc[i][j][r] = 0.f;

    const uint32_t aoff = ((lane & 15) * HPITCH + (lane >> 4) * 8) * 2;
    const uint32_t boff = ((lane & 7) * HPITCH + ((lane >> 3) & 1) * 8) * 2;

    const int lr = tid >> 3;
    const int lc = tid & 7;

    auto load_stage = [&](int s, int k0) {
        const uint32_t stg = sbase + s * HSTAGE;
#pragma unroll
        for (int i = 0; i < 4; i++) {
            int r = lr + i * 32;
            CP_ASYNC16(stg + r * HPITCHB + lc * 16,
                       A + (size_t)(m0 + r) * K + k0 + lc * 8);
            CP_ASYNC16(stg + HSTG + r * HPITCHB + lc * 16,
                       B + (size_t)(n0 + r) * K + k0 + lc * 8);
        }
    };

    const int nkt = K / 64;

    load_stage(0, 0);
    asm volatile("cp.async.commit_group;");

    for (int kt = 0; kt < nkt; kt++) {
        const int cur = kt & 1;
        if (kt + 1 < nkt) {
            load_stage(cur ^ 1, (kt + 1) * 64);
            asm volatile("cp.async.commit_group;");
            asm volatile("cp.async.wait_group 1;");
        } else {
            asm volatile("cp.async.wait_group 0;");
        }
        __syncthreads();

        const uint32_t stgA = sbase + cur * HSTAGE + wm * 64 * HPITCHB + aoff;
        const uint32_t stgB = sbase + cur * HSTAGE + HSTG + wn * 32 * HPITCHB + boff;

#pragma unroll
        for (int ks = 0; ks < 4; ks++) {
            uint32_t af[4][4], bf[4][2];
#pragma unroll
            for (int mi = 0; mi < 4; mi++)
                LDSM_X4(af[mi], stgA + mi * 16 * HPITCHB + ks * 32);
#pragma unroll
            for (int ni = 0; ni < 4; ni++)
                LDSM_X2(bf[ni], stgB + ni * 8 * HPITCHB + ks * 32);
#pragma unroll
            for (int mi = 0; mi < 4; mi++)
#pragma unroll
                for (int ni = 0; ni < 4; ni++)
                    MMA_F16(acc[mi][ni], af[mi], bf[ni]);
        }
        __syncthreads();
    }

    if (VSPLIT && n0 >= VOFF) {
        // V tile: write transposed fp16 directly to vT[b*kvh][dim][tok]
#pragma unroll
        for (int mi = 0; mi < 4; mi++) {
            int row = m0 + wm * 64 + mi * 16 + g;
            int bb  = row >> 10;            // /TT
            int tok = row & (TT - 1);
#pragma unroll
            for (int ni = 0; ni < 4; ni++) {
                int col = n0 + wn * 32 + ni * 8 + 2 * tg;
                int cc  = col - VOFF;
                int kvh = cc / HD;
                int d   = cc % HD;
                __half* dst = vT + ((size_t)(bb * NKV + kvh) * HD + d) * TT + tok;
                dst[0]      = __float2half_rn(acc[mi][ni][0]);
                dst[TT]     = __float2half_rn(acc[mi][ni][1]);
                dst[8]      = __float2half_rn(acc[mi][ni][2]);
                dst[TT + 8] = __float2half_rn(acc[mi][ni][3]);
            }
        }
    } else {
#pragma unroll
        for (int mi = 0; mi < 4; mi++) {
            int row = m0 + wm * 64 + mi * 16 + g;
#pragma unroll
            for (int ni = 0; ni < 4; ni++) {
                int col = n0 + wn * 32 + ni * 8 + 2 * tg;
                if (sizeof(OutT) == 2) {
                    __half* cp = (__half*)C;
                    *(__half2*)&cp[(size_t)row * N + col] =
                        __floats2half2_rn(acc[mi][ni][0], acc[mi][ni][1]);
                    *(__half2*)&cp[(size_t)(row + 8) * N + col] =
                        __floats2half2_rn(acc[mi][ni][2], acc[mi][ni][3]);
                } else {
                    float* cp = (float*)C;
                    *(float2*)&cp[(size_t)row * N + col] =
                        make_float2(acc[mi][ni][0], acc[mi][ni][1]);
                    *(float2*)&cp[(size_t)(row + 8) * N + col] =
                        make_float2(acc[mi][ni][2], acc[mi][ni][3]);
                }
            }
        }
    }
}

// ---------------------------------------------------------------------------
// Fused RMSNorm + RoPE for BOTH q and k in one launch, fp16 in-place.
// ---------------------------------------------------------------------------
__global__ void norm_rope_qk_kernel(__half* __restrict__ qkv,
                                    const float* __restrict__ wq,
                                    const float* __restrict__ wk,
                                    const float* __restrict__ cosb,
                                    const float* __restrict__ sinb,
                                    int rows_q, int rows_total, float qscale)
{
    int gw = (blockIdx.x * blockDim.x + threadIdx.x) >> 5;
    if (gw >= rows_total) return;
    int lane = threadIdx.x & 31;

    const float* w;
    __half* row;
    float outscale;
    int tok;
    if (gw < rows_q) {
        int h = gw & (NHEADS - 1);
        tok = gw >> 5;
        row = qkv + (size_t)tok * QKVN + (size_t)h * HD;
        w = wq; outscale = qscale;
    } else {
        int gk = gw - rows_q;
        int h = gk & (NKV - 1);
        tok = gk >> 3;
        row = qkv + (size_t)tok * QKVN + QDIM + (size_t)h * HD;
        w = wk; outscale = 1.0f;
    }
    int tpos = tok & (TT - 1);

    float2 v0 = __half22float2(*(const __half2*)&row[2 * lane]);
    float2 v1 = make_float2(0.f, 0.f);
    if (lane < 16) v1 = __half22float2(*(const __half2*)&row[2 * (lane + 32)]);

    float ss = v0.x*v0.x + v0.y*v0.y + v1.x*v1.x + v1.y*v1.y;
#pragma unroll
    for (int off = 16; off; off >>= 1)
        ss += __shfl_xor_sync(0xffffffffu, ss, off);
    float inv = outscale / sqrtf(ss * (1.0f / HD) + 1e-6f);

    const float* cr = cosb + (size_t)tpos * HD;
    const float* sr = sinb + (size_t)tpos * HD;
    {
        int i2 = 2 * lane;
        float xr = w[i2] * v0.x * inv;
        float xi = w[i2 + 1] * v0.y * inv;
        float o0 = xr * cr[i2]     - xi * sr[i2];
        float o1 = xr * sr[i2 + 1] + xi * cr[i2 + 1];
        *(__half2*)&row[i2] = __floats2half2_rn(o0, o1);
    }
    if (lane < 16) {
        int i2 = 2 * (lane + 32);
        float xr = w[i2] * v1.x * inv;
        float xi = w[i2 + 1] * v1.y * inv;
        float o0 = xr * cr[i2]     - xi * sr[i2];
        float o1 = xr * sr[i2 + 1] + xi * cr[i2 + 1];
        *(__half2*)&row[i2] = __floats2half2_rn(o0, o1);
    }
}

// ---------------------------------------------------------------------------
// fp16 tensor-core flash attention (FlashAttention-2 style).
// Block = (128 q-rows, head, batch), 8 warps x 16 rows. 1 CTA/SM (reg-heavy).
// ---------------------------------------------------------------------------
#define KP   52
#define VP   36
#define K_STG_B   (64 * 104 * 2)
#define VT_STG_B  (96 * 72 * 2)
#define AKV_STG_B (K_STG_B + VT_STG_B)
#define PP   36
#define ATTN_SMEM_B (2 * AKV_STG_B + 8 * 16 * PP * 4)   // 72704

__global__ __launch_bounds__(256, 1)
void attn_h_kernel(const __half* __restrict__ qk, const __half* __restrict__ vT,
                   __half* __restrict__ o)
{
    extern __shared__ char smem[];
    const int tid  = threadIdx.x;
    const int warp = tid >> 5;
    const int lane = tid & 31;
    const int g    = lane >> 2;
    const int tg   = lane & 3;

    const int qt = blockIdx.x;
    const int h  = blockIdx.y;
    const int b  = blockIdx.z;
    const int kvh = h >> 2;
    const int q0 = qt * 128;
    const int row0 = warp * 16;

    const __half* qb  = qk + (size_t)b * TT * QKVN + (size_t)h * HD;
    const __half* kb  = qk + (size_t)b * TT * QKVN + QDIM + (size_t)kvh * HD;
    const __half* vTb = vT + (size_t)(b * NKV + kvh) * HD * TT;
    __half*       ob  = o  + (size_t)b * TT * QDIM + (size_t)h * HD;

    uint32_t* Psu = (uint32_t*)(smem + 2 * AKV_STG_B) + warp * 16 * PP;

    // --- Q fragments (pre-scaled fp16 in global) ---
    uint32_t qf[6][4];
    {
        const __half* r0p = qb + (size_t)(q0 + row0 + g)     * QKVN;
        const __half* r8p = qb + (size_t)(q0 + row0 + g + 8) * QKVN;
#pragma unroll
        for (int ks = 0; ks < 6; ks++) {
            qf[ks][0] = *(const uint32_t*)&r0p[ks * 16 + 2 * tg];
            qf[ks][1] = *(const uint32_t*)&r8p[ks * 16 + 2 * tg];
            qf[ks][2] = *(const uint32_t*)&r0p[ks * 16 + 2 * tg + 8];
            qf[ks][3] = *(const uint32_t*)&r8p[ks * 16 + 2 * tg + 8];
        }
    }

    float oacc[12][4];
#pragma unroll
    for (int i = 0; i < 12; i++)
#pragma unroll
        for (int j = 0; j < 4; j++) oacc[i][j] = 0.f;

    float m0 = -1e30f, m1 = -1e30f, l0 = 0.f, l1 = 0.f;
    const int nt = 2 * qt + 2;

    auto load_kv = [&](int stage, int kt) {
        const uint32_t stg = smem_u32(smem) + stage * AKV_STG_B;
#pragma unroll
        for (int j = 0; j < 6; j++) {
            int c = tid + j * 256;
            if (c < 768) {
                int r = c / 12, cc = c % 12;
                CP_ASYNC16(stg + r * 208 + cc * 16,
                           kb + (size_t)(kt * 64 + r) * QKVN + cc * 8);
            } else {
                int c2 = c - 768;
                int r = c2 >> 3, cc = c2 & 7;
                CP_ASYNC16(stg + K_STG_B + r * 144 + cc * 16,
                           vTb + (size_t)r * TT + kt * 64 + cc * 8);
            }
        }
    };

    load_kv(0, 0);
    asm volatile("cp.async.commit_group;");

    for (int kt = 0; kt < nt; kt++) {
        int cur = kt & 1;
        if (kt + 1 < nt) {
            load_kv(cur ^ 1, kt + 1);
            asm volatile("cp.async.commit_group;");
            asm volatile("cp.async.wait_group 1;");
        } else {
            asm volatile("cp.async.wait_group 0;");
        }
        __syncthreads();

        const uint32_t* Ksu = (const uint32_t*)(smem + cur * AKV_STG_B);
        const uint32_t* VTu = (const uint32_t*)(smem + cur * AKV_STG_B + K_STG_B);

        // --- S = Q K^T (16x64 per warp) ---
        float sacc[8][4];
#pragma unroll
        for (int i = 0; i < 8; i++)
#pragma unroll
            for (int j = 0; j < 4; j++) sacc[i][j] = 0.f;

#pragma unroll
        for (int ks = 0; ks < 6; ks++) {
#pragma unroll
            for (int ni = 0; ni < 8; ni++) {
                uint32_t bf[2];
                bf[0] = Ksu[(ni * 8 + g) * KP + ks * 8 + tg];
                bf[1] = Ksu[(ni * 8 + g) * KP + ks * 8 + tg + 4];
                MMA_F16(sacc[ni], qf[ks], bf);
            }
        }

        // --- Causal mask ---
        const int rg = q0 + row0 + g;
        const int r8 = rg + 8;
        if (kt >= 2 * qt) {
#pragma unroll
            for (int ni = 0; ni < 8; ni++) {
                int kbase = kt * 64 + ni * 8 + 2 * tg;
                if (kbase     > rg) sacc[ni][0] = -1e30f;
                if (kbase + 1 > rg) sacc[ni][1] = -1e30f;
                if (kbase     > r8) sacc[ni][2] = -1e30f;
                if (kbase + 1 > r8) sacc[ni][3] = -1e30f;
            }
        }

        // --- Online softmax (rows g, g+8) ---
        float mx0 = -1e30f, mx1 = -1e30f;
#pragma unroll
        for (int ni = 0; ni < 8; ni++) {
            mx0 = fmaxf(mx0, fmaxf(sacc[ni][0], sacc[ni][1]));
            mx1 = fmaxf(mx1, fmaxf(sacc[ni][2], sacc[ni][3]));
        }
        mx0 = fmaxf(mx0, __shfl_xor_sync(0xffffffffu, mx0, 1));
        mx0 = fmaxf(mx0, __shfl_xor_sync(0xffffffffu, mx0, 2));
        mx1 = fmaxf(mx1, __shfl_xor_sync(0xffffffffu, mx1, 1));
        mx1 = fmaxf(mx1, __shfl_xor_sync(0xffffffffu, mx1, 2));

        float mn0 = fmaxf(m0, mx0), mn1 = fmaxf(m1, mx1);
        float a0 = __expf(m0 - mn0), a1 = __expf(m1 - mn1);
        float s0 = 0.f, s1 = 0.f;
#pragma unroll
        for (int ni = 0; ni < 8; ni++) {
            float p0 = __expf(sacc[ni][0] - mn0);
            float p1 = __expf(sacc[ni][1] - mn0);
            float p2 = __expf(sacc[ni][2] - mn1);
            float p3 = __expf(sacc[ni][3] - mn1);
            sacc[ni][0] = p0; sacc[ni][1] = p1;
            sacc[ni][2] = p2; sacc[ni][3] = p3;
            s0 += p0 + p1; s1 += p2 + p3;
        }
        s0 += __shfl_xor_sync(0xffffffffu, s0, 1);
        s0 += __shfl_xor_sync(0xffffffffu, s0, 2);
        s1 += __shfl_xor_sync(0xffffffffu, s1, 1);
        s1 += __shfl_xor_sync(0xffffffffu, s1, 2);
        l0 = l0 * a0 + s0; l1 = l1 * a1 + s1;
        m0 = mn0; m1 = mn1;

#pragma unroll
        for (int nn = 0; nn < 12; nn++) {
            oacc[nn][0] *= a0; oacc[nn][1] *= a0;
            oacc[nn][2] *= a1; oacc[nn][3] *= a1;
        }

        // --- P -> per-warp smem (fp16) ---
        __syncwarp();
#pragma unroll
        for (int ni = 0; ni < 8; ni++) {
            __half2 h0 = __floats2half2_rn(sacc[ni][0], sacc[ni][1]);
            __half2 h1 = __floats2half2_rn(sacc[ni][2], sacc[ni][3]);
            Psu[g * PP + ni * 4 + tg]       = *(uint32_t*)&h0;
            Psu[(g + 8) * PP + ni * 4 + tg] = *(uint32_t*)&h1;
        }
        __syncwarp();

        // --- O += P V (V^T layout) ---
#pragma unroll
        for (int kk = 0; kk < 4; kk++) {
            uint32_t af[4];
            af[0] = Psu[g * PP + kk * 8 + tg];
            af[1] = Psu[(g + 8) * PP + kk * 8 + tg];
            af[2] = Psu[g * PP + kk * 8 + tg + 4];
            af[3] = Psu[(g + 8) * PP + kk * 8 + tg + 4];
#pragma unroll
            for (int nn = 0; nn < 12; nn++) {
                uint32_t bf[2];
                bf[0] = VTu[(nn * 8 + g) * VP + kk * 8 + tg];
                bf[1] = VTu[(nn * 8 + g) * VP + kk * 8 + tg + 4];
                MMA_F16(oacc[nn], af, bf);
            }
        }
        __syncthreads();   // protect KV stage reuse
    }

    // --- Epilogue: normalize, convert fp16, store ---
    float i0 = 1.f / l0, i1 = 1.f / l1;
    __half2* o0 = (__half2*)(ob + (size_t)(q0 + row0 + g)     * QDIM);
    __half2* o8 = (__half2*)(ob + (size_t)(q0 + row0 + g + 8) * QDIM);
#pragma unroll
    for (int nn = 0; nn < 12; nn++) {
        o0[nn * 4 + tg] = __floats2half2_rn(oacc[nn][0] * i0, oacc[nn][1] * i0);
        o8[nn * 4 + tg] = __floats2half2_rn(oacc[nn][2] * i1, oacc[nn][3] * i1);
    }
}

// ---------------------------------------------------------------------------
// Launch
// ---------------------------------------------------------------------------
extern "C" void kernel_launch(void* const* d_in, const int* in_sizes, int n_in,
                              void* d_out, int out_size)
{
    const float* x    = (const float*)d_in[0];
    const float* wq   = (const float*)d_in[2];
    const float* wk   = (const float*)d_in[3];
    const float* wv   = (const float*)d_in[4];
    const float* wo   = (const float*)d_in[5];
    const float* qnw  = (const float*)d_in[6];
    const float* knw  = (const float*)d_in[7];
    const float* cosb = (const float*)d_in[8];
    const float* sinb = (const float*)d_in[9];
    float* out = (float*)d_out;

    void *pxh, *pwh, *pwoh, *pqkvh, *pvT, *pah;
    cudaGetSymbolAddress(&pxh,   g_xh);
    cudaGetSymbolAddress(&pwh,   g_wh);
    cudaGetSymbolAddress(&pwoh,  g_woh);
    cudaGetSymbolAddress(&pqkvh, g_qkvh);
    cudaGetSymbolAddress(&pvT,   g_vT);
    cudaGetSymbolAddress(&pah,   g_attnh);
    __half* hx   = (__half*)pxh;
    __half* hw   = (__half*)pwh;
    __half* hwo  = (__half*)pwoh;
    __half* hqkv = (__half*)pqkvh;
    __half* hvT  = (__half*)pvT;
    __half* ha   = (__half*)pah;

    cudaFuncSetAttribute((void*)gemm_h<__half, true>,
                         cudaFuncAttributeMaxDynamicSharedMemorySize, HGEMM_SMEM);
    cudaFuncSetAttribute((void*)gemm_h<float, false>,
                         cudaFuncAttributeMaxDynamicSharedMemorySize, HGEMM_SMEM);
    cudaFuncSetAttribute(attn_h_kernel, cudaFuncAttributeMaxDynamicSharedMemorySize,
                         ATTN_SMEM_B);

    dim3 blk(256);

    // Fused fp16 conversion pre-pass (x, wq, wk, wv, wo) — one launch.
    {
        const int cx  = NTOK * DMODEL / 16;
        const int cwq = QDIM * DMODEL / 16;
        const int cwk = KVDIM * DMODEL / 16;
        const int cwv = KVDIM * DMODEL / 16;
        const int cwo = DMODEL * QDIM / 16;
        const int total = cx + cwq + cwk + cwv + cwo;
        f2h_multi<<<(total + 255) / 256, blk>>>(
            x,  hx,  cx,
            wq, hw,  cwq,
            wk, hw + (size_t)QDIM * DMODEL, cwk,
            wv, hw + (size_t)(QDIM + KVDIM) * DMODEL, cwv,
            wo, hwo, cwo);
    }

    // Fused QKV projection: q|k -> g_qkvh, v-tiles transposed -> g_vT
    gemm_h<__half, true><<<dim3(QKVN / 128, NTOK / 128), blk, HGEMM_SMEM>>>(
        hx, hw, hqkv, hvT, NTOK, QKVN, DMODEL);

    // RMSNorm + RoPE in place, q and k in one launch (q scaled by 1/sqrt(96))
    {
        const float scale = 0.1020620726159658f;
        int rows_q = NTOK * NHEADS;
        int rows_total = rows_q + NTOK * NKV;
        norm_rope_qk_kernel<<<(rows_total * 32 + 255) / 256, blk>>>(
            hqkv, qnw, knw, cosb, sinb, rows_q, rows_total, scale);
    }

    // Attention (fp16 HMMA, 1 CTA/SM — reg-heavy, do NOT cap regs)
    attn_h_kernel<<<dim3(TT / 128, NHEADS, BB), blk, ATTN_SMEM_B>>>(hqkv, hvT, ha);

    // Output projection (fp32 out)
    gemm_h<float, false><<<dim3(QDIM / 128, NTOK / 128), blk, HGEMM_SMEM>>>(
        ha, hwo, out, nullptr, NTOK, QDIM, DMODEL);
}

// round 16
// speedup vs baseline: 1.1874x; 1.0624x over previous
#include <cuda_runtime.h>
#include <cuda_fp16.h>
#include <math.h>
#include <stdint.h>

// Problem constants
#define BB 2
#define TT 1024
#define DMODEL 3072
#define NHEADS 32
#define NKV 8
#define HD 96
#define NTOK 2048
#define QDIM 3072
#define KVDIM 768
#define QKVN 4608            // fused projection width (q|k|v)
#define VOFF (QDIM + KVDIM)  // 3840: start of v columns

// Scratch (static device globals; no allocation allowed)
__device__ __half g_xh[(size_t)NTOK*DMODEL];
__device__ __half g_wh[(size_t)QKVN*DMODEL];     // [wq;wk;wv] fp16
__device__ __half g_woh[(size_t)DMODEL*QDIM];
__device__ __half g_qkvh[(size_t)NTOK*QKVN];     // q|k (v-tiles bypassed to g_vT)
__device__ __half g_vT[(size_t)BB*NKV*HD*TT];    // V transposed: [b*kvh][dim][tok]
__device__ __half g_attnh[(size_t)NTOK*QDIM];    // attention output fp16

// ---------------------------------------------------------------------------
// Helpers
// ---------------------------------------------------------------------------
__device__ __forceinline__ uint32_t smem_u32(const void* p) {
    uint32_t a;
    asm("{ .reg .u64 t; cvta.to.shared.u64 t, %1; cvt.u32.u64 %0, t; }"
        : "=r"(a) : "l"(p));
    return a;
}

#define MMA_F16(acc, a, b)                                                    \
    asm volatile(                                                             \
        "mma.sync.aligned.m16n8k16.row.col.f32.f16.f16.f32 "                  \
        "{%0,%1,%2,%3}, {%4,%5,%6,%7}, {%8,%9}, {%0,%1,%2,%3};"               \
        : "+f"((acc)[0]), "+f"((acc)[1]), "+f"((acc)[2]), "+f"((acc)[3])      \
        : "r"((a)[0]), "r"((a)[1]), "r"((a)[2]), "r"((a)[3]),                 \
          "r"((b)[0]), "r"((b)[1]))

#define LDSM_X4(r, addr)                                                      \
    asm volatile("ldmatrix.sync.aligned.m8n8.x4.shared.b16 {%0,%1,%2,%3}, [%4];" \
        : "=r"((r)[0]), "=r"((r)[1]), "=r"((r)[2]), "=r"((r)[3]) : "r"(addr))

#define LDSM_X2(r, addr)                                                      \
    asm volatile("ldmatrix.sync.aligned.m8n8.x2.shared.b16 {%0,%1}, [%2];"    \
        : "=r"((r)[0]), "=r"((r)[1]) : "r"(addr))

#define CP_ASYNC16(dst, src)                                                  \
    asm volatile("cp.async.cg.shared.global [%0], [%1], 16;" :: "r"(dst), "l"(src))

// ---------------------------------------------------------------------------
// Fused fp32 -> fp16 conversion for all 5 tensors in one launch.
// ---------------------------------------------------------------------------
__device__ __forceinline__ uint4 pack8h(float4 a, float4 b) {
    __half2 h0 = __floats2half2_rn(a.x, a.y);
    __half2 h1 = __floats2half2_rn(a.z, a.w);
    __half2 h2 = __floats2half2_rn(b.x, b.y);
    __half2 h3 = __floats2half2_rn(b.z, b.w);
    uint4 r;
    r.x = *(uint32_t*)&h0; r.y = *(uint32_t*)&h1;
    r.z = *(uint32_t*)&h2; r.w = *(uint32_t*)&h3;
    return r;
}

__global__ void f2h_multi(const float* __restrict__ s0, __half* __restrict__ d0, int c0,
                          const float* __restrict__ s1, __half* __restrict__ d1, int c1,
                          const float* __restrict__ s2, __half* __restrict__ d2, int c2,
                          const float* __restrict__ s3, __half* __restrict__ d3, int c3,
                          const float* __restrict__ s4, __half* __restrict__ d4, int c4)
{
    int i = blockIdx.x * blockDim.x + threadIdx.x;
    const float* s; __half* d; int off;
    int e0 = c0, e1 = e0 + c1, e2 = e1 + c2, e3 = e2 + c3, e4 = e3 + c4;
    if      (i < e0) { s = s0; d = d0; off = i; }
    else if (i < e1) { s = s1; d = d1; off = i - e0; }
    else if (i < e2) { s = s2; d = d2; off = i - e1; }
    else if (i < e3) { s = s3; d = d3; off = i - e2; }
    else if (i < e4) { s = s4; d = d4; off = i - e3; }
    else return;

    const float4* sp = (const float4*)s + (size_t)off * 4;
    float4 a = sp[0], b = sp[1], c = sp[2], e = sp[3];
    uint4* dp = (uint4*)d + (size_t)off * 2;
    dp[0] = pack8h(a, b);
    dp[1] = pack8h(c, e);
}

// ---------------------------------------------------------------------------
// fp16 tensor-core GEMM: C[M,N] = A[M,K] * B[N,K]^T, fp32 accumulate.
// Block 128x128, K-tile 64, 8 warps (2x4), warp 64x32, mma m16n8k16,
// ldmatrix fragment loads, 2-stage cp.async double buffer (2 CTAs/SM).
// VSPLIT: tiles with n0 >= VOFF write transposed fp16 to vT instead of C.
// ---------------------------------------------------------------------------
#define HPITCH  72                    // halves per smem row
#define HPITCHB 144                   // bytes (16B-aligned: 16*9)
#define HSTG    (128 * HPITCHB)       // 18432 per matrix
#define HSTAGE  (2 * HSTG)            // 36864 per stage (A+B)
#define HGEMM_SMEM (2 * HSTAGE)       // 73728

template <typename OutT, bool VSPLIT>
__global__ __launch_bounds__(256)
void gemm_h(const __half* __restrict__ A, const __half* __restrict__ B,
            OutT* __restrict__ C, __half* __restrict__ vT, int M, int N, int K)
{
    extern __shared__ char smem[];
    const uint32_t sbase = smem_u32(smem);
    const int tid  = threadIdx.x;
    const int warp = tid >> 5;
    const int lane = tid & 31;
    const int g  = lane >> 2;
    const int tg = lane & 3;
    const int wm = warp & 1;
    const int wn = warp >> 1;
    const int m0 = blockIdx.y * 128;
    const int n0 = blockIdx.x * 128;

    float acc[4][4][4];
#pragma unroll
    for (int i = 0; i < 4; i++)
#pragma unroll
        for (int j = 0; j < 4; j++)
#pragma unroll
            for (int r = 0; r < 4; r++) acc[i][j][r] = 0.f;

    const uint32_t aoff = ((lane & 15) * HPITCH + (lane >> 4) * 8) * 2;
    const uint32_t boff = ((lane & 7) * HPITCH + ((lane >> 3) & 1) * 8) * 2;

    const int lr = tid >> 3;
    const int lc = tid & 7;

    auto load_stage = [&](int s, int k0) {
        const uint32_t stg = sbase + s * HSTAGE;
#pragma unroll
        for (int i = 0; i < 4; i++) {
            int r = lr + i * 32;
            CP_ASYNC16(stg + r * HPITCHB + lc * 16,
                       A + (size_t)(m0 + r) * K + k0 + lc * 8);
            CP_ASYNC16(stg + HSTG + r * HPITCHB + lc * 16,
                       B + (size_t)(n0 + r) * K + k0 + lc * 8);
        }
    };

    const int nkt = K / 64;

    load_stage(0, 0);
    asm volatile("cp.async.commit_group;");

    for (int kt = 0; kt < nkt; kt++) {
        const int cur = kt & 1;
        if (kt + 1 < nkt) {
            load_stage(cur ^ 1, (kt + 1) * 64);
            asm volatile("cp.async.commit_group;");
            asm volatile("cp.async.wait_group 1;");
        } else {
            asm volatile("cp.async.wait_group 0;");
        }
        __syncthreads();

        const uint32_t stgA = sbase + cur * HSTAGE + wm * 64 * HPITCHB + aoff;
        const uint32_t stgB = sbase + cur * HSTAGE + HSTG + wn * 32 * HPITCHB + boff;

#pragma unroll
        for (int ks = 0; ks < 4; ks++) {
            uint32_t af[4][4], bf[4][2];
#pragma unroll
            for (int mi = 0; mi < 4; mi++)
                LDSM_X4(af[mi], stgA + mi * 16 * HPITCHB + ks * 32);
#pragma unroll
            for (int ni = 0; ni < 4; ni++)
                LDSM_X2(bf[ni], stgB + ni * 8 * HPITCHB + ks * 32);
#pragma unroll
            for (int mi = 0; mi < 4; mi++)
#pragma unroll
                for (int ni = 0; ni < 4; ni++)
                    MMA_F16(acc[mi][ni], af[mi], bf[ni]);
        }
        __syncthreads();
    }

    if (VSPLIT && n0 >= VOFF) {
        // V tile: write transposed fp16 directly to vT[b*kvh][dim][tok]
#pragma unroll
        for (int mi = 0; mi < 4; mi++) {
            int row = m0 + wm * 64 + mi * 16 + g;
            int bb  = row >> 10;            // /TT
            int tok = row & (TT - 1);
#pragma unroll
            for (int ni = 0; ni < 4; ni++) {
                int col = n0 + wn * 32 + ni * 8 + 2 * tg;
                int cc  = col - VOFF;
                int kvh = cc / HD;
                int d   = cc % HD;
                __half* dst = vT + ((size_t)(bb * NKV + kvh) * HD + d) * TT + tok;
                dst[0]      = __float2half_rn(acc[mi][ni][0]);
                dst[TT]     = __float2half_rn(acc[mi][ni][1]);
                dst[8]      = __float2half_rn(acc[mi][ni][2]);
                dst[TT + 8] = __float2half_rn(acc[mi][ni][3]);
            }
        }
    } else {
#pragma unroll
        for (int mi = 0; mi < 4; mi++) {
            int row = m0 + wm * 64 + mi * 16 + g;
#pragma unroll
            for (int ni = 0; ni < 4; ni++) {
                int col = n0 + wn * 32 + ni * 8 + 2 * tg;
                if (sizeof(OutT) == 2) {
                    __half* cp = (__half*)C;
                    *(__half2*)&cp[(size_t)row * N + col] =
                        __floats2half2_rn(acc[mi][ni][0], acc[mi][ni][1]);
                    *(__half2*)&cp[(size_t)(row + 8) * N + col] =
                        __floats2half2_rn(acc[mi][ni][2], acc[mi][ni][3]);
                } else {
                    float* cp = (float*)C;
                    *(float2*)&cp[(size_t)row * N + col] =
                        make_float2(acc[mi][ni][0], acc[mi][ni][1]);
                    *(float2*)&cp[(size_t)(row + 8) * N + col] =
                        make_float2(acc[mi][ni][2], acc[mi][ni][3]);
                }
            }
        }
    }
}

// ---------------------------------------------------------------------------
// Fused RMSNorm + RoPE for BOTH q and k in one launch, fp16 in-place.
// ---------------------------------------------------------------------------
__global__ void norm_rope_qk_kernel(__half* __restrict__ qkv,
                                    const float* __restrict__ wq,
                                    const float* __restrict__ wk,
                                    const float* __restrict__ cosb,
                                    const float* __restrict__ sinb,
                                    int rows_q, int rows_total, float qscale)
{
    int gw = (blockIdx.x * blockDim.x + threadIdx.x) >> 5;
    if (gw >= rows_total) return;
    int lane = threadIdx.x & 31;

    const float* w;
    __half* row;
    float outscale;
    int tok;
    if (gw < rows_q) {
        int h = gw & (NHEADS - 1);
        tok = gw >> 5;
        row = qkv + (size_t)tok * QKVN + (size_t)h * HD;
        w = wq; outscale = qscale;
    } else {
        int gk = gw - rows_q;
        int h = gk & (NKV - 1);
        tok = gk >> 3;
        row = qkv + (size_t)tok * QKVN + QDIM + (size_t)h * HD;
        w = wk; outscale = 1.0f;
    }
    int tpos = tok & (TT - 1);

    float2 v0 = __half22float2(*(const __half2*)&row[2 * lane]);
    float2 v1 = make_float2(0.f, 0.f);
    if (lane < 16) v1 = __half22float2(*(const __half2*)&row[2 * (lane + 32)]);

    float ss = v0.x*v0.x + v0.y*v0.y + v1.x*v1.x + v1.y*v1.y;
#pragma unroll
    for (int off = 16; off; off >>= 1)
        ss += __shfl_xor_sync(0xffffffffu, ss, off);
    float inv = outscale / sqrtf(ss * (1.0f / HD) + 1e-6f);

    const float* cr = cosb + (size_t)tpos * HD;
    const float* sr = sinb + (size_t)tpos * HD;
    {
        int i2 = 2 * lane;
        float xr = w[i2] * v0.x * inv;
        float xi = w[i2 + 1] * v0.y * inv;
        float o0 = xr * cr[i2]     - xi * sr[i2];
        float o1 = xr * sr[i2 + 1] + xi * cr[i2 + 1];
        *(__half2*)&row[i2] = __floats2half2_rn(o0, o1);
    }
    if (lane < 16) {
        int i2 = 2 * (lane + 32);
        float xr = w[i2] * v1.x * inv;
        float xi = w[i2 + 1] * v1.y * inv;
        float o0 = xr * cr[i2]     - xi * sr[i2];
        float o1 = xr * sr[i2 + 1] + xi * cr[i2 + 1];
        *(__half2*)&row[i2] = __floats2half2_rn(o0, o1);
    }
}

// ---------------------------------------------------------------------------
// fp16 tensor-core flash attention (FlashAttention-2 style).
// 1D grid (512), decoded with qt REVERSED so heavy causal tiles launch first
// (LPT scheduling). 8 warps x 16 q-rows, 1 CTA/SM (reg-heavy).
// ---------------------------------------------------------------------------
#define KP   52
#define VP   36
#define K_STG_B   (64 * 104 * 2)
#define VT_STG_B  (96 * 72 * 2)
#define AKV_STG_B (K_STG_B + VT_STG_B)
#define PP   36
#define ATTN_SMEM_B (2 * AKV_STG_B + 8 * 16 * PP * 4)   // 72704
#define NQT  (TT / 128)                                  // 8

__global__ __launch_bounds__(256, 1)
void attn_h_kernel(const __half* __restrict__ qk, const __half* __restrict__ vT,
                   __half* __restrict__ o)
{
    extern __shared__ char smem[];
    const int tid  = threadIdx.x;
    const int warp = tid >> 5;
    const int lane = tid & 31;
    const int g    = lane >> 2;
    const int tg   = lane & 3;

    // LPT decode: heavy qt first. bx in [0, NQT*NHEADS*BB)
    const int bx = blockIdx.x;
    const int qt = (NQT - 1) - (bx >> 6);     // 64 = NHEADS*BB CTAs per qt
    const int hb = bx & 63;
    const int h  = hb & (NHEADS - 1);
    const int b  = hb >> 5;
    const int kvh = h >> 2;
    const int q0 = qt * 128;
    const int row0 = warp * 16;

    const __half* qb  = qk + (size_t)b * TT * QKVN + (size_t)h * HD;
    const __half* kb  = qk + (size_t)b * TT * QKVN + QDIM + (size_t)kvh * HD;
    const __half* vTb = vT + (size_t)(b * NKV + kvh) * HD * TT;
    __half*       ob  = o  + (size_t)b * TT * QDIM + (size_t)h * HD;

    uint32_t* Psu = (uint32_t*)(smem + 2 * AKV_STG_B) + warp * 16 * PP;

    // --- Q fragments (pre-scaled fp16 in global) ---
    uint32_t qf[6][4];
    {
        const __half* r0p = qb + (size_t)(q0 + row0 + g)     * QKVN;
        const __half* r8p = qb + (size_t)(q0 + row0 + g + 8) * QKVN;
#pragma unroll
        for (int ks = 0; ks < 6; ks++) {
            qf[ks][0] = *(const uint32_t*)&r0p[ks * 16 + 2 * tg];
            qf[ks][1] = *(const uint32_t*)&r8p[ks * 16 + 2 * tg];
            qf[ks][2] = *(const uint32_t*)&r0p[ks * 16 + 2 * tg + 8];
            qf[ks][3] = *(const uint32_t*)&r8p[ks * 16 + 2 * tg + 8];
        }
    }

    float oacc[12][4];
#pragma unroll
    for (int i = 0; i < 12; i++)
#pragma unroll
        for (int j = 0; j < 4; j++) oacc[i][j] = 0.f;

    float m0 = -1e30f, m1 = -1e30f, l0 = 0.f, l1 = 0.f;
    const int nt = 2 * qt + 2;

    auto load_kv = [&](int stage, int kt) {
        const uint32_t stg = smem_u32(smem) + stage * AKV_STG_B;
#pragma unroll
        for (int j = 0; j < 6; j++) {
            int c = tid + j * 256;
            if (c < 768) {
                int r = c / 12, cc = c % 12;
                CP_ASYNC16(stg + r * 208 + cc * 16,
                           kb + (size_t)(kt * 64 + r) * QKVN + cc * 8);
            } else {
                int c2 = c - 768;
                int r = c2 >> 3, cc = c2 & 7;
                CP_ASYNC16(stg + K_STG_B + r * 144 + cc * 16,
                           vTb + (size_t)r * TT + kt * 64 + cc * 8);
            }
        }
    };

    load_kv(0, 0);
    asm volatile("cp.async.commit_group;");

    for (int kt = 0; kt < nt; kt++) {
        int cur = kt & 1;
        if (kt + 1 < nt) {
            load_kv(cur ^ 1, kt + 1);
            asm volatile("cp.async.commit_group;");
            asm volatile("cp.async.wait_group 1;");
        } else {
            asm volatile("cp.async.wait_group 0;");
        }
        __syncthreads();

        const uint32_t* Ksu = (const uint32_t*)(smem + cur * AKV_STG_B);
        const uint32_t* VTu = (const uint32_t*)(smem + cur * AKV_STG_B + K_STG_B);

        // --- S = Q K^T (16x64 per warp) ---
        float sacc[8][4];
#pragma unroll
        for (int i = 0; i < 8; i++)
#pragma unroll
            for (int j = 0; j < 4; j++) sacc[i][j] = 0.f;

#pragma unroll
        for (int ks = 0; ks < 6; ks++) {
#pragma unroll
            for (int ni = 0; ni < 8; ni++) {
                uint32_t bf[2];
                bf[0] = Ksu[(ni * 8 + g) * KP + ks * 8 + tg];
                bf[1] = Ksu[(ni * 8 + g) * KP + ks * 8 + tg + 4];
                MMA_F16(sacc[ni], qf[ks], bf);
            }
        }

        // --- Causal mask ---
        const int rg = q0 + row0 + g;
        const int r8 = rg + 8;
        if (kt >= 2 * qt) {
#pragma unroll
            for (int ni = 0; ni < 8; ni++) {
                int kbase = kt * 64 + ni * 8 + 2 * tg;
                if (kbase     > rg) sacc[ni][0] = -1e30f;
                if (kbase + 1 > rg) sacc[ni][1] = -1e30f;
                if (kbase     > r8) sacc[ni][2] = -1e30f;
                if (kbase + 1 > r8) sacc[ni][3] = -1e30f;
            }
        }

        // --- Online softmax (rows g, g+8) ---
        float mx0 = -1e30f, mx1 = -1e30f;
#pragma unroll
        for (int ni = 0; ni < 8; ni++) {
            mx0 = fmaxf(mx0, fmaxf(sacc[ni][0], sacc[ni][1]));
            mx1 = fmaxf(mx1, fmaxf(sacc[ni][2], sacc[ni][3]));
        }
        mx0 = fmaxf(mx0, __shfl_xor_sync(0xffffffffu, mx0, 1));
        mx0 = fmaxf(mx0, __shfl_xor_sync(0xffffffffu, mx0, 2));
        mx1 = fmaxf(mx1, __shfl_xor_sync(0xffffffffu, mx1, 1));
        mx1 = fmaxf(mx1, __shfl_xor_sync(0xffffffffu, mx1, 2));

        float mn0 = fmaxf(m0, mx0), mn1 = fmaxf(m1, mx1);
        float a0 = __expf(m0 - mn0), a1 = __expf(m1 - mn1);
        float s0 = 0.f, s1 = 0.f;
#pragma unroll
        for (int ni = 0; ni < 8; ni++) {
            float p0 = __expf(sacc[ni][0] - mn0);
            float p1 = __expf(sacc[ni][1] - mn0);
            float p2 = __expf(sacc[ni][2] - mn1);
            float p3 = __expf(sacc[ni][3] - mn1);
            sacc[ni][0] = p0; sacc[ni][1] = p1;
            sacc[ni][2] = p2; sacc[ni][3] = p3;
            s0 += p0 + p1; s1 += p2 + p3;
        }
        s0 += __shfl_xor_sync(0xffffffffu, s0, 1);
        s0 += __shfl_xor_sync(0xffffffffu, s0, 2);
        s1 += __shfl_xor_sync(0xffffffffu, s1, 1);
        s1 += __shfl_xor_sync(0xffffffffu, s1, 2);
        l0 = l0 * a0 + s0; l1 = l1 * a1 + s1;
        m0 = mn0; m1 = mn1;

#pragma unroll
        for (int nn = 0; nn < 12; nn++) {
            oacc[nn][0] *= a0; oacc[nn][1] *= a0;
            oacc[nn][2] *= a1; oacc[nn][3] *= a1;
        }

        // --- P -> per-warp smem (fp16) ---
        __syncwarp();
#pragma unroll
        for (int ni = 0; ni < 8; ni++) {
            __half2 h0 = __floats2half2_rn(sacc[ni][0], sacc[ni][1]);
            __half2 h1 = __floats2half2_rn(sacc[ni][2], sacc[ni][3]);
            Psu[g * PP + ni * 4 + tg]       = *(uint32_t*)&h0;
            Psu[(g + 8) * PP + ni * 4 + tg] = *(uint32_t*)&h1;
        }
        __syncwarp();

        // --- O += P V (V^T layout) ---
#pragma unroll
        for (int kk = 0; kk < 4; kk++) {
            uint32_t af[4];
            af[0] = Psu[g * PP + kk * 8 + tg];
            af[1] = Psu[(g + 8) * PP + kk * 8 + tg];
            af[2] = Psu[g * PP + kk * 8 + tg + 4];
            af[3] = Psu[(g + 8) * PP + kk * 8 + tg + 4];
#pragma unroll
            for (int nn = 0; nn < 12; nn++) {
                uint32_t bf[2];
                bf[0] = VTu[(nn * 8 + g) * VP + kk * 8 + tg];
                bf[1] = VTu[(nn * 8 + g) * VP + kk * 8 + tg + 4];
                MMA_F16(oacc[nn], af, bf);
            }
        }
        __syncthreads();   // protect KV stage reuse
    }

    // --- Epilogue: normalize, convert fp16, store ---
    float i0 = 1.f / l0, i1 = 1.f / l1;
    __half2* o0 = (__half2*)(ob + (size_t)(q0 + row0 + g)     * QDIM);
    __half2* o8 = (__half2*)(ob + (size_t)(q0 + row0 + g + 8) * QDIM);
#pragma unroll
    for (int nn = 0; nn < 12; nn++) {
        o0[nn * 4 + tg] = __floats2half2_rn(oacc[nn][0] * i0, oacc[nn][1] * i0);
        o8[nn * 4 + tg] = __floats2half2_rn(oacc[nn][2] * i1, oacc[nn][3] * i1);
    }
}

// ---------------------------------------------------------------------------
// Launch
// ---------------------------------------------------------------------------
extern "C" void kernel_launch(void* const* d_in, const int* in_sizes, int n_in,
                              void* d_out, int out_size)
{
    const float* x    = (const float*)d_in[0];
    const float* wq   = (const float*)d_in[2];
    const float* wk   = (const float*)d_in[3];
    const float* wv   = (const float*)d_in[4];
    const float* wo   = (const float*)d_in[5];
    const float* qnw  = (const float*)d_in[6];
    const float* knw  = (const float*)d_in[7];
    const float* cosb = (const float*)d_in[8];
    const float* sinb = (const float*)d_in[9];
    float* out = (float*)d_out;

    void *pxh, *pwh, *pwoh, *pqkvh, *pvT, *pah;
    cudaGetSymbolAddress(&pxh,   g_xh);
    cudaGetSymbolAddress(&pwh,   g_wh);
    cudaGetSymbolAddress(&pwoh,  g_woh);
    cudaGetSymbolAddress(&pqkvh, g_qkvh);
    cudaGetSymbolAddress(&pvT,   g_vT);
    cudaGetSymbolAddress(&pah,   g_attnh);
    __half* hx   = (__half*)pxh;
    __half* hw   = (__half*)pwh;
    __half* hwo  = (__half*)pwoh;
    __half* hqkv = (__half*)pqkvh;
    __half* hvT  = (__half*)pvT;
    __half* ha   = (__half*)pah;

    cudaFuncSetAttribute((void*)gemm_h<__half, true>,
                         cudaFuncAttributeMaxDynamicSharedMemorySize, HGEMM_SMEM);
    cudaFuncSetAttribute((void*)gemm_h<float, false>,
                         cudaFuncAttributeMaxDynamicSharedMemorySize, HGEMM_SMEM);
    cudaFuncSetAttribute(attn_h_kernel, cudaFuncAttributeMaxDynamicSharedMemorySize,
                         ATTN_SMEM_B);

    dim3 blk(256);

    // Fused fp16 conversion pre-pass (x, wq, wk, wv, wo) — one launch.
    {
        const int cx  = NTOK * DMODEL / 16;
        const int cwq = QDIM * DMODEL / 16;
        const int cwk = KVDIM * DMODEL / 16;
        const int cwv = KVDIM * DMODEL / 16;
        const int cwo = DMODEL * QDIM / 16;
        const int total = cx + cwq + cwk + cwv + cwo;
        f2h_multi<<<(total + 255) / 256, blk>>>(
            x,  hx,  cx,
            wq, hw,  cwq,
            wk, hw + (size_t)QDIM * DMODEL, cwk,
            wv, hw + (size_t)(QDIM + KVDIM) * DMODEL, cwv,
            wo, hwo, cwo);
    }

    // Fused QKV projection: q|k -> g_qkvh, v-tiles transposed -> g_vT
    gemm_h<__half, true><<<dim3(QKVN / 128, NTOK / 128), blk, HGEMM_SMEM>>>(
        hx, hw, hqkv, hvT, NTOK, QKVN, DMODEL);

    // RMSNorm + RoPE in place, q and k in one launch (q scaled by 1/sqrt(96))
    {
        const float scale = 0.1020620726159658f;
        int rows_q = NTOK * NHEADS;
        int rows_total = rows_q + NTOK * NKV;
        norm_rope_qk_kernel<<<(rows_total * 32 + 255) / 256, blk>>>(
            hqkv, qnw, knw, cosb, sinb, rows_q, rows_total, scale);
    }

    // Attention (fp16 HMMA, 1D grid with heavy-tiles-first LPT order)
    attn_h_kernel<<<NQT * NHEADS * BB, blk, ATTN_SMEM_B>>>(hqkv, hvT, ha);

    // Output projection (fp32 out)
    gemm_h<float, false><<<dim3(QDIM / 128, NTOK / 128), blk, HGEMM_SMEM>>>(
        ha, hwo, out, nullptr, NTOK, QDIM, DMODEL);
}